// round 15
// baseline (speedup 1.0000x reference)
#include <cuda_runtime.h>
#include <cuda_bf16.h>
#include <cstdint>

// Problem constants: B=8, N=4096, C=512, K=8192
#define M_TOTAL 32768
#define K_CB    8192
#define C_DIM   512

#define BM 128
#define BN 128
#define BK 32                       // bf16 elems per chunk (64B per row)
#define NCHUNK (C_DIM / BK)         // 16
#define NSTAGE 3
#define ROWP 40                     // smem pitch in bf16 elems (80B) -> conflict-free
#define MARGIN 2.0f
#define NBLK16 (K_CB / 16)          // 512 paired entries per row (two 8-wide mins each)

#define ASZB ((BM * ROWP) * 2)      // 10240 bytes per A stage
#define BSZB ((BN * ROWP) * 2)      // 10240 bytes per B stage
#define BOFF (NSTAGE * ASZB)        // 30720
#define CSQOFF (BOFF + NSTAGE * BSZB) // 61440
#define SMEM_TOTAL (CSQOFF + BN * 4)  // 61952  (x3 CTAs = 186KB/SM)

// ---------------- device scratch (allocation-free) ----------------
__device__ __nv_bfloat16      g_xb[(size_t)M_TOTAL * C_DIM];   // 32MB
__device__ __nv_bfloat16      g_cbb[(size_t)K_CB * C_DIM];     // 8MB
__device__ float              g_cbsq[K_CB];
__device__ unsigned long long g_blockmin[(size_t)M_TOTAL * NBLK16]; // 128MB paired ord scores

// ---------------- helpers ----------------
__device__ __forceinline__ uint32_t smem_u32(const void* p) {
    uint32_t a;
    asm("{ .reg .u64 t; cvta.to.shared.u64 t, %1; cvt.u32.u64 %0, t; }" : "=r"(a) : "l"(p));
    return a;
}
__device__ __forceinline__ void cpasync16(uint32_t s, const void* g) {
    asm volatile("{ .reg .u64 gg; cvta.to.global.u64 gg, %1; cp.async.cg.shared.global [%0], [gg], 16; }"
                 :: "r"(s), "l"(g) : "memory");
}
#define CP_COMMIT()  asm volatile("cp.async.commit_group;" ::: "memory")
#define CP_WAIT(n)   asm volatile("cp.async.wait_group %0;" :: "n"(n) : "memory")

__device__ __forceinline__ void ldsm4(uint32_t* r, uint32_t a) {
    asm volatile("ldmatrix.sync.aligned.m8n8.x4.shared.b16 {%0,%1,%2,%3}, [%4];"
                 : "=r"(r[0]), "=r"(r[1]), "=r"(r[2]), "=r"(r[3]) : "r"(a));
}
__device__ __forceinline__ void mma16816(float* d, const uint32_t* a, const uint32_t* b) {
    asm volatile("mma.sync.aligned.m16n8k16.row.col.f32.bf16.bf16.f32 "
                 "{%0,%1,%2,%3}, {%4,%5,%6,%7}, {%8,%9}, {%0,%1,%2,%3};"
                 : "+f"(d[0]), "+f"(d[1]), "+f"(d[2]), "+f"(d[3])
                 : "r"(a[0]), "r"(a[1]), "r"(a[2]), "r"(a[3]), "r"(b[0]), "r"(b[1]));
}
__device__ __forceinline__ unsigned f2ord(float f) {
    unsigned u = __float_as_uint(f);
    return (u & 0x80000000u) ? ~u : (u | 0x80000000u);
}
__device__ __forceinline__ float ord2f(unsigned o) {
    unsigned u = (o & 0x80000000u) ? (o & 0x7FFFFFFFu) : ~o;
    return __uint_as_float(u);
}
__device__ __forceinline__ unsigned umin2(unsigned a, unsigned b) { return a < b ? a : b; }

// ---------------------------------------------------------------------------
__global__ void convert_kernel(const float* __restrict__ X, const float* __restrict__ CB) {
    const long NX = (long)M_TOTAL * C_DIM / 4;
    const long NC = (long)K_CB * C_DIM / 4;
    long i = (long)blockIdx.x * blockDim.x + threadIdx.x;
    if (i < NX) {
        float4 v = ((const float4*)X)[i];
        __nv_bfloat162* o = (__nv_bfloat162*)g_xb;
        o[2 * i]     = __floats2bfloat162_rn(v.x, v.y);
        o[2 * i + 1] = __floats2bfloat162_rn(v.z, v.w);
    } else if (i < NX + NC) {
        long j = i - NX;
        float4 v = ((const float4*)CB)[j];
        __nv_bfloat162* o = (__nv_bfloat162*)g_cbb;
        o[2 * j]     = __floats2bfloat162_rn(v.x, v.y);
        o[2 * j + 1] = __floats2bfloat162_rn(v.z, v.w);
    }
}

__global__ void cbsq_kernel(const float* __restrict__ cb) {
    int row = blockIdx.x * 8 + (threadIdx.x >> 5);
    int lane = threadIdx.x & 31;
    const float* r = cb + (size_t)row * C_DIM;
    float s = 0.f;
    #pragma unroll
    for (int c = lane; c < C_DIM; c += 32) { float v = r[c]; s = fmaf(v, v, s); }
    #pragma unroll
    for (int o = 16; o; o >>= 1) s += __shfl_xor_sync(0xffffffffu, s, o);
    if (lane == 0) g_cbsq[row] = s;
}

// ---------------------------------------------------------------------------
// Coarse bf16 HMMA GEMM + paired 8-wide block-min epilogue
//   16 warps 4(M)x4(N), warp tile 32x32, BK=32, 3-stage cp.async, 3 CTAs/SM
// ---------------------------------------------------------------------------
__global__ void __launch_bounds__(256, 3) gemm_kernel() {
    extern __shared__ __align__(16) char smem[];
    const uint32_t sb = smem_u32(smem);
    float* s_csq = (float*)(smem + CSQOFF);

    const int tid  = threadIdx.x;
    const int wid  = tid >> 5, lane = tid & 31;
    const int wy   = wid >> 2, wx = wid & 3;     // warp grid 4x4
    const int m0   = wy * 32,  n0 = wx * 32;
    const int mbase = blockIdx.y * BM;
    const int nbase = blockIdx.x * BN;

    if (tid < BN) s_csq[tid] = g_cbsq[nbase + tid];

    float acc[2][4][4];
    #pragma unroll
    for (int i = 0; i < 2; i++)
        #pragma unroll
        for (int j = 0; j < 4; j++)
            #pragma unroll
            for (int q = 0; q < 4; q++) acc[i][j][q] = 0.f;

    // ldmatrix lane addressing (proven mapping)
    const int a_r = (lane & 7) + ((lane >> 3) & 1) * 8;
    const int a_c = (lane >> 4) * 8;
    const int b_r = (lane & 7) + (lane >> 4) * 8;
    const int b_c = ((lane >> 3) & 1) * 8;

    uint32_t aBase[NSTAGE], bBase[NSTAGE];
    #pragma unroll
    for (int s = 0; s < NSTAGE; s++) {
        aBase[s] = sb + s * ASZB + (uint32_t)((m0 + a_r) * ROWP + a_c) * 2;
        bBase[s] = sb + BOFF + s * BSZB + (uint32_t)((n0 + b_r) * ROWP + b_c) * 2;
    }

    // cp.async loader: thread -> (row, 16B segment), 2x16B per operand
    const int ld_row = tid >> 2, ld_seg = tid & 3;
    auto load_chunk = [&](int s, int cc) {
        const uint32_t soA = sb + s * ASZB + (uint32_t)(ld_row * ROWP + ld_seg * 8) * 2;
        const uint32_t soB = sb + BOFF + s * BSZB + (uint32_t)(ld_row * ROWP + ld_seg * 8) * 2;
        const uint32_t rstep = (uint32_t)(64 * ROWP) * 2;   // +64 rows
        const size_t gstep = (size_t)64 * C_DIM;
        const __nv_bfloat16* gA = g_xb + (size_t)(mbase + ld_row) * C_DIM + cc + ld_seg * 8;
        const __nv_bfloat16* gB = g_cbb + (size_t)(nbase + ld_row) * C_DIM + cc + ld_seg * 8;
        cpasync16(soA, gA);                 cpasync16(soB, gB);
        cpasync16(soA + rstep, gA + gstep); cpasync16(soB + rstep, gB + gstep);
    };

    load_chunk(0, 0); CP_COMMIT();
    load_chunk(1, BK); CP_COMMIT();

    #pragma unroll 1
    for (int ch = 0; ch < NCHUNK; ch++) {
        if (ch < NCHUNK - 1) { CP_WAIT(1); } else { CP_WAIT(0); }
        __syncthreads();
        if (ch + 2 < NCHUNK) { load_chunk((ch + 2) % NSTAGE, (ch + 2) * BK); CP_COMMIT(); }

        const uint32_t aS = aBase[ch % NSTAGE], bS = bBase[ch % NSTAGE];
        #pragma unroll
        for (int ks = 0; ks < 2; ks++) {
            uint32_t a[2][4];
            #pragma unroll
            for (int mf = 0; mf < 2; mf++)
                ldsm4(a[mf], aS + (uint32_t)(mf * 16 * ROWP) * 2 + ks * 32);
            uint32_t b[4][2];
            #pragma unroll
            for (int np = 0; np < 2; np++) {
                uint32_t r[4];
                ldsm4(r, bS + (uint32_t)(np * 16 * ROWP) * 2 + ks * 32);
                b[np * 2 + 0][0] = r[0]; b[np * 2 + 0][1] = r[1];
                b[np * 2 + 1][0] = r[2]; b[np * 2 + 1][1] = r[3];
            }
            #pragma unroll
            for (int mf = 0; mf < 2; mf++)
                #pragma unroll
                for (int nf = 0; nf < 4; nf++)
                    mma16816(acc[mf][nf], a[mf], b[nf]);
        }
    }

    // ---- epilogue: paired 8-wide ord-score mins, one 64-bit store / 16 cols ----
    const int qrow = lane >> 2;
    const int qcol = (lane & 3) * 2;
    #pragma unroll
    for (int mf = 0; mf < 2; mf++) {
        const int row0 = mbase + m0 + mf * 16 + qrow;
        unsigned pu0[4], pu1[4];
        #pragma unroll
        for (int nf = 0; nf < 4; nf++) {
            const int cb_loc = n0 + nf * 8 + qcol;
            const float cs0 = s_csq[cb_loc], cs1 = s_csq[cb_loc + 1];
            unsigned u0 = umin2(f2ord(fmaf(2.f, acc[mf][nf][0], cs0)),
                                f2ord(fmaf(2.f, acc[mf][nf][1], cs1)));
            unsigned u1 = umin2(f2ord(fmaf(2.f, acc[mf][nf][2], cs0)),
                                f2ord(fmaf(2.f, acc[mf][nf][3], cs1)));
            #pragma unroll
            for (int o = 1; o <= 2; o <<= 1) {
                u0 = umin2(u0, __shfl_xor_sync(0xffffffffu, u0, o));
                u1 = umin2(u1, __shfl_xor_sync(0xffffffffu, u1, o));
            }
            pu0[nf] = u0; pu1[nf] = u1;
        }
        if ((lane & 3) == 0) {
            #pragma unroll
            for (int p = 0; p < 2; p++) {
                const int blk = (nbase + n0 + p * 16) >> 4;
                unsigned long long v0 = (unsigned long long)pu0[2*p] |
                                        ((unsigned long long)pu0[2*p+1] << 32);
                unsigned long long v1 = (unsigned long long)pu1[2*p] |
                                        ((unsigned long long)pu1[2*p+1] << 32);
                __stcs(&g_blockmin[(size_t)row0 * NBLK16 + blk], v0);
                __stcs(&g_blockmin[(size_t)(row0 + 8) * NBLK16 + blk], v1);
            }
        }
    }
}

// ---------------------------------------------------------------------------
// Exact fp32 rescue + output gather — one warp per row, two-pass (R13 best):
// pass 1 scans + caches paired block mins; pass 2 rescores qualifying halves.
// ---------------------------------------------------------------------------
__global__ void __launch_bounds__(256) rescue_kernel(const float* __restrict__ X,
                                                     const float* __restrict__ CB,
                                                     float* __restrict__ out, int out_size) {
    const int row = blockIdx.x * 8 + (threadIdx.x >> 5);
    const int lane = threadIdx.x & 31;

    float x[16];
    {
        const float4* xr = (const float4*)(X + (size_t)row * C_DIM + lane * 16);
        float4 a = xr[0], b = xr[1], c = xr[2], d = xr[3];
        x[0]=a.x; x[1]=a.y; x[2]=a.z; x[3]=a.w; x[4]=b.x; x[5]=b.y; x[6]=b.z; x[7]=b.w;
        x[8]=c.x; x[9]=c.y; x[10]=c.z; x[11]=c.w; x[12]=d.x; x[13]=d.y; x[14]=d.z; x[15]=d.w;
    }

    const unsigned long long* bm = g_blockmin + (size_t)row * NBLK16;

    // Pass 1: cache 512 paired entries (16 per lane) + row min over both halves
    unsigned long long vloc[16];
    unsigned mymin = 0xFFFFFFFFu;
    #pragma unroll
    for (int r = 0; r < 16; r++) {
        vloc[r] = __ldcs(&bm[r * 32 + lane]);
        mymin = umin2(mymin, umin2((unsigned)vloc[r], (unsigned)(vloc[r] >> 32)));
    }
    #pragma unroll
    for (int o = 16; o; o >>= 1)
        mymin = umin2(mymin, __shfl_xor_sync(0xffffffffu, mymin, o));
    const unsigned thr = f2ord(ord2f(mymin) + MARGIN);

    // Pass 2: exact rescore of qualifying 8-wide halves (4 codewords at a time)
    float bests = 3.4e38f; int bestk = 0x7FFFFFFF;
    #pragma unroll 1
    for (int r = 0; r < 16; r++) {
        const unsigned long long v = vloc[r];
        const bool any = ((unsigned)v <= thr) | ((unsigned)(v >> 32) <= thr);
        unsigned mask = __ballot_sync(0xffffffffu, any);
        while (mask) {
            int b = __ffs(mask) - 1;
            mask &= mask - 1;
            const unsigned long long vb = __shfl_sync(0xffffffffu, v, b);
            const int k16 = (r * 32 + b) * 16;
            #pragma unroll 1
            for (int h = 0; h < 2; h++) {
                const unsigned hv = (h == 0) ? (unsigned)vb : (unsigned)(vb >> 32);
                if (hv > thr) continue;
                #pragma unroll 1
                for (int g = 0; g < 2; g++) {
                    const int kg = k16 + h * 8 + g * 4;
                    float p[4];
                    #pragma unroll
                    for (int j = 0; j < 4; j++) {
                        const float4* cr = (const float4*)(CB + (size_t)(kg + j) * C_DIM + lane * 16);
                        float4 c0 = cr[0], c1 = cr[1], c2 = cr[2], c3 = cr[3];
                        float q = 0.f;
                        q = fmaf(x[0],  c0.x, q); q = fmaf(x[1],  c0.y, q);
                        q = fmaf(x[2],  c0.z, q); q = fmaf(x[3],  c0.w, q);
                        q = fmaf(x[4],  c1.x, q); q = fmaf(x[5],  c1.y, q);
                        q = fmaf(x[6],  c1.z, q); q = fmaf(x[7],  c1.w, q);
                        q = fmaf(x[8],  c2.x, q); q = fmaf(x[9],  c2.y, q);
                        q = fmaf(x[10], c2.z, q); q = fmaf(x[11], c2.w, q);
                        q = fmaf(x[12], c3.x, q); q = fmaf(x[13], c3.y, q);
                        q = fmaf(x[14], c3.z, q); q = fmaf(x[15], c3.w, q);
                        p[j] = q;
                    }
                    #pragma unroll
                    for (int o = 16; o; o >>= 1) {
                        p[0] += __shfl_xor_sync(0xffffffffu, p[0], o);
                        p[1] += __shfl_xor_sync(0xffffffffu, p[1], o);
                        p[2] += __shfl_xor_sync(0xffffffffu, p[2], o);
                        p[3] += __shfl_xor_sync(0xffffffffu, p[3], o);
                    }
                    #pragma unroll
                    for (int j = 0; j < 4; j++) {
                        float s = fmaf(2.f, p[j], __ldg(&g_cbsq[kg + j]));
                        int k = kg + j;
                        if (s < bests || (s == bests && k < bestk)) { bests = s; bestk = k; }
                    }
                }
            }
        }
    }

    // ---- output: all lanes hold identical bestk (fully-reduced scores) ----
    const size_t BNC = (size_t)M_TOTAL * C_DIM;
    const float4* cbrow = (const float4*)(CB + (size_t)bestk * C_DIM);
    float4* o0 = (float4*)(out + (size_t)row * C_DIM);
    float4* o1 = (float4*)(out + BNC + (size_t)row * C_DIM);
    const bool dup = ((size_t)out_size >= 2 * BNC);
    #pragma unroll
    for (int i = 0; i < 4; i++) {
        float4 v = cbrow[lane + 32 * i];
        o0[lane + 32 * i] = v;
        if (dup) o1[lane + 32 * i] = v;
    }
    if (lane == 0 && (size_t)out_size >= 2 * BNC + M_TOTAL)
        out[2 * BNC + row] = (float)bestk;
}

// ---------------------------------------------------------------------------
extern "C" void kernel_launch(void* const* d_in, const int* in_sizes, int n_in,
                              void* d_out, int out_size) {
    const float* X  = (const float*)d_in[0];
    const float* CB = (const float*)d_in[1];
    if (n_in >= 2 && in_sizes[0] == K_CB * C_DIM && in_sizes[1] == M_TOTAL * C_DIM) {
        X  = (const float*)d_in[1];
        CB = (const float*)d_in[0];
    }
    float* out = (float*)d_out;

    cudaFuncSetAttribute(gemm_kernel, cudaFuncAttributeMaxDynamicSharedMemorySize, SMEM_TOTAL);

    const long nconv = ((long)M_TOTAL * C_DIM + (long)K_CB * C_DIM) / 4;
    convert_kernel<<<(unsigned)((nconv + 255) / 256), 256>>>(X, CB);
    cbsq_kernel<<<K_CB / 8, 256>>>(CB);
    gemm_kernel<<<dim3(K_CB / BN, M_TOTAL / BM), 256, SMEM_TOTAL>>>();
    rescue_kernel<<<M_TOTAL / 8, 256>>>(X, CB, out, out_size);
}

// round 16
// speedup vs baseline: 30.2773x; 30.2773x over previous
#include <cuda_runtime.h>
#include <cuda_bf16.h>
#include <cstdint>

// Problem constants: B=8, N=4096, C=512, K=8192
#define M_TOTAL 32768
#define K_CB    8192
#define C_DIM   512

#define BM 128
#define BN 128
#define BK 32                       // bf16 elems per chunk (64B per row)
#define NCHUNK (C_DIM / BK)         // 16
#define NSTAGE 4
#define ROWP 40                     // smem pitch in bf16 elems (80B) -> conflict-free
#define MARGIN 2.0f
#define NBLK16 (K_CB / 16)          // 512 paired entries per row (two 8-wide mins each)

#define ASZB ((BM * ROWP) * 2)      // 10240 bytes per A stage
#define BSZB ((BN * ROWP) * 2)      // 10240 bytes per B stage
#define BOFF (NSTAGE * ASZB)        // 40960
#define CSQOFF (BOFF + NSTAGE * BSZB) // 81920
#define SMEM_TOTAL (CSQOFF + BN * 4)  // 82432

// ---------------- device scratch (allocation-free) ----------------
__device__ __nv_bfloat16      g_xb[(size_t)M_TOTAL * C_DIM];   // 32MB
__device__ __nv_bfloat16      g_cbb[(size_t)K_CB * C_DIM];     // 8MB
__device__ float              g_cbsq[K_CB];
__device__ unsigned long long g_blockmin[(size_t)M_TOTAL * NBLK16]; // 128MB paired ord scores

// ---------------- helpers ----------------
__device__ __forceinline__ uint32_t smem_u32(const void* p) {
    uint32_t a;
    asm("{ .reg .u64 t; cvta.to.shared.u64 t, %1; cvt.u32.u64 %0, t; }" : "=r"(a) : "l"(p));
    return a;
}
__device__ __forceinline__ void cpasync16(uint32_t s, const void* g) {
    asm volatile("{ .reg .u64 gg; cvta.to.global.u64 gg, %1; cp.async.cg.shared.global [%0], [gg], 16; }"
                 :: "r"(s), "l"(g) : "memory");
}
#define CP_COMMIT()  asm volatile("cp.async.commit_group;" ::: "memory")
#define CP_WAIT(n)   asm volatile("cp.async.wait_group %0;" :: "n"(n) : "memory")

__device__ __forceinline__ void ldsm4(uint32_t* r, uint32_t a) {
    asm volatile("ldmatrix.sync.aligned.m8n8.x4.shared.b16 {%0,%1,%2,%3}, [%4];"
                 : "=r"(r[0]), "=r"(r[1]), "=r"(r[2]), "=r"(r[3]) : "r"(a));
}
__device__ __forceinline__ void mma16816(float* d, const uint32_t* a, const uint32_t* b) {
    asm volatile("mma.sync.aligned.m16n8k16.row.col.f32.bf16.bf16.f32 "
                 "{%0,%1,%2,%3}, {%4,%5,%6,%7}, {%8,%9}, {%0,%1,%2,%3};"
                 : "+f"(d[0]), "+f"(d[1]), "+f"(d[2]), "+f"(d[3])
                 : "r"(a[0]), "r"(a[1]), "r"(a[2]), "r"(a[3]), "r"(b[0]), "r"(b[1]));
}
__device__ __forceinline__ unsigned f2ord(float f) {
    unsigned u = __float_as_uint(f);
    return (u & 0x80000000u) ? ~u : (u | 0x80000000u);
}
__device__ __forceinline__ float ord2f(unsigned o) {
    unsigned u = (o & 0x80000000u) ? (o & 0x7FFFFFFFu) : ~o;
    return __uint_as_float(u);
}
__device__ __forceinline__ unsigned umin2(unsigned a, unsigned b) { return a < b ? a : b; }

// ---------------------------------------------------------------------------
__global__ void convert_kernel(const float* __restrict__ X, const float* __restrict__ CB) {
    const long NX = (long)M_TOTAL * C_DIM / 4;
    const long NC = (long)K_CB * C_DIM / 4;
    long i = (long)blockIdx.x * blockDim.x + threadIdx.x;
    if (i < NX) {
        float4 v = ((const float4*)X)[i];
        __nv_bfloat162* o = (__nv_bfloat162*)g_xb;
        o[2 * i]     = __floats2bfloat162_rn(v.x, v.y);
        o[2 * i + 1] = __floats2bfloat162_rn(v.z, v.w);
    } else if (i < NX + NC) {
        long j = i - NX;
        float4 v = ((const float4*)CB)[j];
        __nv_bfloat162* o = (__nv_bfloat162*)g_cbb;
        o[2 * j]     = __floats2bfloat162_rn(v.x, v.y);
        o[2 * j + 1] = __floats2bfloat162_rn(v.z, v.w);
    }
}

__global__ void cbsq_kernel(const float* __restrict__ cb) {
    int row = blockIdx.x * 8 + (threadIdx.x >> 5);
    int lane = threadIdx.x & 31;
    const float* r = cb + (size_t)row * C_DIM;
    float s = 0.f;
    #pragma unroll
    for (int c = lane; c < C_DIM; c += 32) { float v = r[c]; s = fmaf(v, v, s); }
    #pragma unroll
    for (int o = 16; o; o >>= 1) s += __shfl_xor_sync(0xffffffffu, s, o);
    if (lane == 0) g_cbsq[row] = s;
}

// ---------------------------------------------------------------------------
// Coarse bf16 HMMA GEMM (R9/R11 mainloop) + paired 8-wide block-min epilogue
//   8 warps 2(M)x4(N), warp tile 64x32, BK=32, 4-stage cp.async, 2 CTAs/SM
// ---------------------------------------------------------------------------
__global__ void __launch_bounds__(256, 2) gemm_kernel() {
    extern __shared__ __align__(16) char smem[];
    const uint32_t sb = smem_u32(smem);
    float* s_csq = (float*)(smem + CSQOFF);

    const int tid  = threadIdx.x;
    const int wid  = tid >> 5, lane = tid & 31;
    const int wy   = wid >> 2, wx = wid & 3;
    const int m0   = wy * 64,  n0 = wx * 32;
    const int mbase = blockIdx.y * BM;
    const int nbase = blockIdx.x * BN;

    if (tid < BN) s_csq[tid] = g_cbsq[nbase + tid];

    float acc[4][4][4];
    #pragma unroll
    for (int i = 0; i < 4; i++)
        #pragma unroll
        for (int j = 0; j < 4; j++)
            #pragma unroll
            for (int q = 0; q < 4; q++) acc[i][j][q] = 0.f;

    const int a_r = (lane & 7) + ((lane >> 3) & 1) * 8;
    const int a_c = (lane >> 4) * 8;
    const int b_r = (lane & 7) + (lane >> 4) * 8;
    const int b_c = ((lane >> 3) & 1) * 8;

    uint32_t aBase[NSTAGE], bBase[NSTAGE];
    #pragma unroll
    for (int s = 0; s < NSTAGE; s++) {
        aBase[s] = sb + s * ASZB + (uint32_t)((m0 + a_r) * ROWP + a_c) * 2;
        bBase[s] = sb + BOFF + s * BSZB + (uint32_t)((n0 + b_r) * ROWP + b_c) * 2;
    }

    const int ld_row = tid >> 2, ld_seg = tid & 3;
    auto load_chunk = [&](int s, int cc) {
        const uint32_t soA = sb + s * ASZB + (uint32_t)(ld_row * ROWP + ld_seg * 8) * 2;
        const uint32_t soB = sb + BOFF + s * BSZB + (uint32_t)(ld_row * ROWP + ld_seg * 8) * 2;
        const uint32_t rstep = (uint32_t)(64 * ROWP) * 2;
        const size_t gstep = (size_t)64 * C_DIM;
        const __nv_bfloat16* gA = g_xb + (size_t)(mbase + ld_row) * C_DIM + cc + ld_seg * 8;
        const __nv_bfloat16* gB = g_cbb + (size_t)(nbase + ld_row) * C_DIM + cc + ld_seg * 8;
        cpasync16(soA, gA);                 cpasync16(soB, gB);
        cpasync16(soA + rstep, gA + gstep); cpasync16(soB + rstep, gB + gstep);
    };

    load_chunk(0, 0); CP_COMMIT();
    load_chunk(1, BK); CP_COMMIT();
    load_chunk(2, 2 * BK); CP_COMMIT();

    for (int cb = 0; cb < NCHUNK; cb += NSTAGE) {
        #pragma unroll
        for (int i = 0; i < NSTAGE; i++) {
            const int ch = cb + i;
            if (ch < NCHUNK - 2)      { CP_WAIT(2); }
            else if (ch == NCHUNK - 2){ CP_WAIT(1); }
            else                      { CP_WAIT(0); }
            __syncthreads();
            if (ch + 3 < NCHUNK) { load_chunk((ch + 3) & 3, (ch + 3) * BK); CP_COMMIT(); }

            const uint32_t aS = aBase[i], bS = bBase[i];
            #pragma unroll
            for (int ks = 0; ks < 2; ks++) {
                uint32_t a[4][4];
                #pragma unroll
                for (int mf = 0; mf < 4; mf++)
                    ldsm4(a[mf], aS + (uint32_t)(mf * 16 * ROWP) * 2 + ks * 32);
                uint32_t b[4][2];
                #pragma unroll
                for (int np = 0; np < 2; np++) {
                    uint32_t r[4];
                    ldsm4(r, bS + (uint32_t)(np * 16 * ROWP) * 2 + ks * 32);
                    b[np * 2 + 0][0] = r[0]; b[np * 2 + 0][1] = r[1];
                    b[np * 2 + 1][0] = r[2]; b[np * 2 + 1][1] = r[3];
                }
                #pragma unroll
                for (int mf = 0; mf < 4; mf++)
                    #pragma unroll
                    for (int nf = 0; nf < 4; nf++)
                        mma16816(acc[mf][nf], a[mf], b[nf]);
            }
        }
    }

    // ---- epilogue: paired 8-wide ord-score mins, one 64-bit store / 16 cols ----
    const int qrow = lane >> 2;
    const int qcol = (lane & 3) * 2;
    #pragma unroll
    for (int mf = 0; mf < 4; mf++) {
        const int row0 = mbase + m0 + mf * 16 + qrow;
        unsigned pu0[4], pu1[4];
        #pragma unroll
        for (int nf = 0; nf < 4; nf++) {
            const int cb_loc = n0 + nf * 8 + qcol;
            const float cs0 = s_csq[cb_loc], cs1 = s_csq[cb_loc + 1];
            unsigned u0 = umin2(f2ord(fmaf(2.f, acc[mf][nf][0], cs0)),
                                f2ord(fmaf(2.f, acc[mf][nf][1], cs1)));
            unsigned u1 = umin2(f2ord(fmaf(2.f, acc[mf][nf][2], cs0)),
                                f2ord(fmaf(2.f, acc[mf][nf][3], cs1)));
            #pragma unroll
            for (int o = 1; o <= 2; o <<= 1) {
                u0 = umin2(u0, __shfl_xor_sync(0xffffffffu, u0, o));
                u1 = umin2(u1, __shfl_xor_sync(0xffffffffu, u1, o));
            }
            pu0[nf] = u0; pu1[nf] = u1;
        }
        if ((lane & 3) == 0) {
            #pragma unroll
            for (int p = 0; p < 2; p++) {
                const int blk = (nbase + n0 + p * 16) >> 4;
                unsigned long long v0 = (unsigned long long)pu0[2*p] |
                                        ((unsigned long long)pu0[2*p+1] << 32);
                unsigned long long v1 = (unsigned long long)pu1[2*p] |
                                        ((unsigned long long)pu1[2*p+1] << 32);
                __stcs(&g_blockmin[(size_t)row0 * NBLK16 + blk], v0);
                __stcs(&g_blockmin[(size_t)(row0 + 8) * NBLK16 + blk], v1);
            }
        }
    }
}

// ---------------------------------------------------------------------------
// Exact fp32 rescue + output gather — one warp per row, two-pass:
// pass 1 scans + caches paired block mins; pass 2 rescores qualifying halves
// (4 interleaved codeword chains to hide latency).
// ---------------------------------------------------------------------------
__global__ void __launch_bounds__(256) rescue_kernel(const float* __restrict__ X,
                                                     const float* __restrict__ CB,
                                                     float* __restrict__ out, int out_size) {
    const int row = blockIdx.x * 8 + (threadIdx.x >> 5);
    const int lane = threadIdx.x & 31;

    float x[16];
    {
        const float4* xr = (const float4*)(X + (size_t)row * C_DIM + lane * 16);
        float4 a = xr[0], b = xr[1], c = xr[2], d = xr[3];
        x[0]=a.x; x[1]=a.y; x[2]=a.z; x[3]=a.w; x[4]=b.x; x[5]=b.y; x[6]=b.z; x[7]=b.w;
        x[8]=c.x; x[9]=c.y; x[10]=c.z; x[11]=c.w; x[12]=d.x; x[13]=d.y; x[14]=d.z; x[15]=d.w;
    }

    const unsigned long long* bm = g_blockmin + (size_t)row * NBLK16;

    // Pass 1: cache 512 paired entries (16 per lane) + row min over both halves
    unsigned long long vloc[16];
    unsigned mymin = 0xFFFFFFFFu;
    #pragma unroll
    for (int r = 0; r < 16; r++) {
        vloc[r] = __ldcs(&bm[r * 32 + lane]);
        mymin = umin2(mymin, umin2((unsigned)vloc[r], (unsigned)(vloc[r] >> 32)));
    }
    #pragma unroll
    for (int o = 16; o; o >>= 1)
        mymin = umin2(mymin, __shfl_xor_sync(0xffffffffu, mymin, o));
    const unsigned thr = f2ord(ord2f(mymin) + MARGIN);

    // Pass 2: exact rescore of qualifying 8-wide halves (4 codewords at a time)
    float bests = 3.4e38f; int bestk = 0x7FFFFFFF;
    #pragma unroll 1
    for (int r = 0; r < 16; r++) {
        const unsigned long long v = vloc[r];
        const bool any = ((unsigned)v <= thr) | ((unsigned)(v >> 32) <= thr);
        unsigned mask = __ballot_sync(0xffffffffu, any);
        while (mask) {
            int b = __ffs(mask) - 1;
            mask &= mask - 1;
            const unsigned long long vb = __shfl_sync(0xffffffffu, v, b);
            const int k16 = (r * 32 + b) * 16;
            #pragma unroll 1
            for (int h = 0; h < 2; h++) {
                const unsigned hv = (h == 0) ? (unsigned)vb : (unsigned)(vb >> 32);
                if (hv > thr) continue;
                #pragma unroll 1
                for (int g = 0; g < 2; g++) {
                    const int kg = k16 + h * 8 + g * 4;
                    float p[4];
                    #pragma unroll
                    for (int j = 0; j < 4; j++) {
                        const float4* cr = (const float4*)(CB + (size_t)(kg + j) * C_DIM + lane * 16);
                        float4 c0 = cr[0], c1 = cr[1], c2 = cr[2], c3 = cr[3];
                        float q = 0.f;
                        q = fmaf(x[0],  c0.x, q); q = fmaf(x[1],  c0.y, q);
                        q = fmaf(x[2],  c0.z, q); q = fmaf(x[3],  c0.w, q);
                        q = fmaf(x[4],  c1.x, q); q = fmaf(x[5],  c1.y, q);
                        q = fmaf(x[6],  c1.z, q); q = fmaf(x[7],  c1.w, q);
                        q = fmaf(x[8],  c2.x, q); q = fmaf(x[9],  c2.y, q);
                        q = fmaf(x[10], c2.z, q); q = fmaf(x[11], c2.w, q);
                        q = fmaf(x[12], c3.x, q); q = fmaf(x[13], c3.y, q);
                        q = fmaf(x[14], c3.z, q); q = fmaf(x[15], c3.w, q);
                        p[j] = q;
                    }
                    #pragma unroll
                    for (int o = 16; o; o >>= 1) {
                        p[0] += __shfl_xor_sync(0xffffffffu, p[0], o);
                        p[1] += __shfl_xor_sync(0xffffffffu, p[1], o);
                        p[2] += __shfl_xor_sync(0xffffffffu, p[2], o);
                        p[3] += __shfl_xor_sync(0xffffffffu, p[3], o);
                    }
                    #pragma unroll
                    for (int j = 0; j < 4; j++) {
                        float s = fmaf(2.f, p[j], __ldg(&g_cbsq[kg + j]));
                        int k = kg + j;
                        if (s < bests || (s == bests && k < bestk)) { bests = s; bestk = k; }
                    }
                }
            }
        }
    }

    // ---- output: all lanes hold identical bestk (fully-reduced scores) ----
    const size_t BNC = (size_t)M_TOTAL * C_DIM;
    const float4* cbrow = (const float4*)(CB + (size_t)bestk * C_DIM);
    float4* o0 = (float4*)(out + (size_t)row * C_DIM);
    float4* o1 = (float4*)(out + BNC + (size_t)row * C_DIM);
    const bool dup = ((size_t)out_size >= 2 * BNC);
    #pragma unroll
    for (int i = 0; i < 4; i++) {
        float4 v = cbrow[lane + 32 * i];
        o0[lane + 32 * i] = v;
        if (dup) o1[lane + 32 * i] = v;
    }
    if (lane == 0 && (size_t)out_size >= 2 * BNC + M_TOTAL)
        out[2 * BNC + row] = (float)bestk;
}

// ---------------------------------------------------------------------------
extern "C" void kernel_launch(void* const* d_in, const int* in_sizes, int n_in,
                              void* d_out, int out_size) {
    const float* X  = (const float*)d_in[0];
    const float* CB = (const float*)d_in[1];
    if (n_in >= 2 && in_sizes[0] == K_CB * C_DIM && in_sizes[1] == M_TOTAL * C_DIM) {
        X  = (const float*)d_in[1];
        CB = (const float*)d_in[0];
    }
    float* out = (float*)d_out;

    cudaFuncSetAttribute(gemm_kernel, cudaFuncAttributeMaxDynamicSharedMemorySize, SMEM_TOTAL);

    const long nconv = ((long)M_TOTAL * C_DIM + (long)K_CB * C_DIM) / 4;
    convert_kernel<<<(unsigned)((nconv + 255) / 256), 256>>>(X, CB);
    cbsq_kernel<<<K_CB / 8, 256>>>(CB);
    gemm_kernel<<<dim3(K_CB / BN, M_TOTAL / BM), 256, SMEM_TOTAL>>>();
    rescue_kernel<<<M_TOTAL / 8, 256>>>(X, CB, out, out_size);
}

// round 17
// speedup vs baseline: 31.5591x; 1.0423x over previous
#include <cuda_runtime.h>
#include <cuda_bf16.h>
#include <cstdint>

// Problem constants: B=8, N=4096, C=512, K=8192
#define M_TOTAL 32768
#define K_CB    8192
#define C_DIM   512

#define BM 128
#define BN 128
#define BK 32                       // bf16 elems per chunk (64B per row)
#define NCHUNK (C_DIM / BK)         // 16
#define NSTAGE 4
#define ROWP 40                     // smem pitch in bf16 elems (80B) -> conflict-free
#define MARGIN 2.0f
#define NBLK32 (K_CB / 32)          // 256 entries per row (four 16-bit 8-wide mins each)

#define ASZB ((BM * ROWP) * 2)      // 10240 bytes per A stage
#define BSZB ((BN * ROWP) * 2)      // 10240 bytes per B stage
#define BOFF (NSTAGE * ASZB)        // 40960
#define CSQOFF (BOFF + NSTAGE * BSZB) // 81920
#define SMEM_TOTAL (CSQOFF + BN * 4)  // 82432

// ---------------- device scratch (allocation-free) ----------------
__device__ __nv_bfloat16      g_xb[(size_t)M_TOTAL * C_DIM];   // 32MB
__device__ __nv_bfloat16      g_cbb[(size_t)K_CB * C_DIM];     // 8MB
__device__ float              g_cbsq[K_CB];
__device__ unsigned long long g_blockmin[(size_t)M_TOTAL * NBLK32]; // 64MB packed 16-bit mins

// ---------------- helpers ----------------
__device__ __forceinline__ uint32_t smem_u32(const void* p) {
    uint32_t a;
    asm("{ .reg .u64 t; cvta.to.shared.u64 t, %1; cvt.u32.u64 %0, t; }" : "=r"(a) : "l"(p));
    return a;
}
__device__ __forceinline__ void cpasync16(uint32_t s, const void* g) {
    asm volatile("{ .reg .u64 gg; cvta.to.global.u64 gg, %1; cp.async.cg.shared.global [%0], [gg], 16; }"
                 :: "r"(s), "l"(g) : "memory");
}
#define CP_COMMIT()  asm volatile("cp.async.commit_group;" ::: "memory")
#define CP_WAIT(n)   asm volatile("cp.async.wait_group %0;" :: "n"(n) : "memory")

__device__ __forceinline__ void ldsm4(uint32_t* r, uint32_t a) {
    asm volatile("ldmatrix.sync.aligned.m8n8.x4.shared.b16 {%0,%1,%2,%3}, [%4];"
                 : "=r"(r[0]), "=r"(r[1]), "=r"(r[2]), "=r"(r[3]) : "r"(a));
}
__device__ __forceinline__ void mma16816(float* d, const uint32_t* a, const uint32_t* b) {
    asm volatile("mma.sync.aligned.m16n8k16.row.col.f32.bf16.bf16.f32 "
                 "{%0,%1,%2,%3}, {%4,%5,%6,%7}, {%8,%9}, {%0,%1,%2,%3};"
                 : "+f"(d[0]), "+f"(d[1]), "+f"(d[2]), "+f"(d[3])
                 : "r"(a[0]), "r"(a[1]), "r"(a[2]), "r"(a[3]), "r"(b[0]), "r"(b[1]));
}
__device__ __forceinline__ unsigned f2ord(float f) {
    unsigned u = __float_as_uint(f);
    return (u & 0x80000000u) ? ~u : (u | 0x80000000u);
}
__device__ __forceinline__ float ord2f(unsigned o) {
    unsigned u = (o & 0x80000000u) ? (o & 0x7FFFFFFFu) : ~o;
    return __uint_as_float(u);
}
__device__ __forceinline__ unsigned umin2(unsigned a, unsigned b) { return a < b ? a : b; }

// ---------------------------------------------------------------------------
__global__ void convert_kernel(const float* __restrict__ X, const float* __restrict__ CB) {
    const long NX = (long)M_TOTAL * C_DIM / 4;
    const long NC = (long)K_CB * C_DIM / 4;
    long i = (long)blockIdx.x * blockDim.x + threadIdx.x;
    if (i < NX) {
        float4 v = ((const float4*)X)[i];
        __nv_bfloat162* o = (__nv_bfloat162*)g_xb;
        o[2 * i]     = __floats2bfloat162_rn(v.x, v.y);
        o[2 * i + 1] = __floats2bfloat162_rn(v.z, v.w);
    } else if (i < NX + NC) {
        long j = i - NX;
        float4 v = ((const float4*)CB)[j];
        __nv_bfloat162* o = (__nv_bfloat162*)g_cbb;
        o[2 * j]     = __floats2bfloat162_rn(v.x, v.y);
        o[2 * j + 1] = __floats2bfloat162_rn(v.z, v.w);
    }
}

__global__ void cbsq_kernel(const float* __restrict__ cb) {
    int row = blockIdx.x * 8 + (threadIdx.x >> 5);
    int lane = threadIdx.x & 31;
    const float* r = cb + (size_t)row * C_DIM;
    float s = 0.f;
    #pragma unroll
    for (int c = lane; c < C_DIM; c += 32) { float v = r[c]; s = fmaf(v, v, s); }
    #pragma unroll
    for (int o = 16; o; o >>= 1) s += __shfl_xor_sync(0xffffffffu, s, o);
    if (lane == 0) g_cbsq[row] = s;
}

// ---------------------------------------------------------------------------
// Coarse bf16 HMMA GEMM (proven mainloop) + packed 16-bit 8-wide block-min
// epilogue: one 64-bit store per 32 columns per row-half.
// ---------------------------------------------------------------------------
__global__ void __launch_bounds__(256, 2) gemm_kernel() {
    extern __shared__ __align__(16) char smem[];
    const uint32_t sb = smem_u32(smem);
    float* s_csq = (float*)(smem + CSQOFF);

    const int tid  = threadIdx.x;
    const int wid  = tid >> 5, lane = tid & 31;
    const int wy   = wid >> 2, wx = wid & 3;
    const int m0   = wy * 64,  n0 = wx * 32;
    const int mbase = blockIdx.y * BM;
    const int nbase = blockIdx.x * BN;

    if (tid < BN) s_csq[tid] = g_cbsq[nbase + tid];

    float acc[4][4][4];
    #pragma unroll
    for (int i = 0; i < 4; i++)
        #pragma unroll
        for (int j = 0; j < 4; j++)
            #pragma unroll
            for (int q = 0; q < 4; q++) acc[i][j][q] = 0.f;

    const int a_r = (lane & 7) + ((lane >> 3) & 1) * 8;
    const int a_c = (lane >> 4) * 8;
    const int b_r = (lane & 7) + (lane >> 4) * 8;
    const int b_c = ((lane >> 3) & 1) * 8;

    uint32_t aBase[NSTAGE], bBase[NSTAGE];
    #pragma unroll
    for (int s = 0; s < NSTAGE; s++) {
        aBase[s] = sb + s * ASZB + (uint32_t)((m0 + a_r) * ROWP + a_c) * 2;
        bBase[s] = sb + BOFF + s * BSZB + (uint32_t)((n0 + b_r) * ROWP + b_c) * 2;
    }

    const int ld_row = tid >> 2, ld_seg = tid & 3;
    auto load_chunk = [&](int s, int cc) {
        const uint32_t soA = sb + s * ASZB + (uint32_t)(ld_row * ROWP + ld_seg * 8) * 2;
        const uint32_t soB = sb + BOFF + s * BSZB + (uint32_t)(ld_row * ROWP + ld_seg * 8) * 2;
        const uint32_t rstep = (uint32_t)(64 * ROWP) * 2;
        const size_t gstep = (size_t)64 * C_DIM;
        const __nv_bfloat16* gA = g_xb + (size_t)(mbase + ld_row) * C_DIM + cc + ld_seg * 8;
        const __nv_bfloat16* gB = g_cbb + (size_t)(nbase + ld_row) * C_DIM + cc + ld_seg * 8;
        cpasync16(soA, gA);                 cpasync16(soB, gB);
        cpasync16(soA + rstep, gA + gstep); cpasync16(soB + rstep, gB + gstep);
    };

    load_chunk(0, 0); CP_COMMIT();
    load_chunk(1, BK); CP_COMMIT();
    load_chunk(2, 2 * BK); CP_COMMIT();

    for (int cb = 0; cb < NCHUNK; cb += NSTAGE) {
        #pragma unroll
        for (int i = 0; i < NSTAGE; i++) {
            const int ch = cb + i;
            if (ch < NCHUNK - 2)      { CP_WAIT(2); }
            else if (ch == NCHUNK - 2){ CP_WAIT(1); }
            else                      { CP_WAIT(0); }
            __syncthreads();
            if (ch + 3 < NCHUNK) { load_chunk((ch + 3) & 3, (ch + 3) * BK); CP_COMMIT(); }

            const uint32_t aS = aBase[i], bS = bBase[i];
            #pragma unroll
            for (int ks = 0; ks < 2; ks++) {
                uint32_t a[4][4];
                #pragma unroll
                for (int mf = 0; mf < 4; mf++)
                    ldsm4(a[mf], aS + (uint32_t)(mf * 16 * ROWP) * 2 + ks * 32);
                uint32_t b[4][2];
                #pragma unroll
                for (int np = 0; np < 2; np++) {
                    uint32_t r[4];
                    ldsm4(r, bS + (uint32_t)(np * 16 * ROWP) * 2 + ks * 32);
                    b[np * 2 + 0][0] = r[0]; b[np * 2 + 0][1] = r[1];
                    b[np * 2 + 1][0] = r[2]; b[np * 2 + 1][1] = r[3];
                }
                #pragma unroll
                for (int mf = 0; mf < 4; mf++)
                    #pragma unroll
                    for (int nf = 0; nf < 4; nf++)
                        mma16816(acc[mf][nf], a[mf], b[nf]);
            }
        }
    }

    // ---- epilogue: four 16-bit 8-wide mins packed per 64-bit store / 32 cols ----
    const int qrow = lane >> 2;
    const int qcol = (lane & 3) * 2;
    #pragma unroll
    for (int mf = 0; mf < 4; mf++) {
        const int row0 = mbase + m0 + mf * 16 + qrow;
        unsigned pu0[4], pu1[4];
        #pragma unroll
        for (int nf = 0; nf < 4; nf++) {
            const int cb_loc = n0 + nf * 8 + qcol;
            const float cs0 = s_csq[cb_loc], cs1 = s_csq[cb_loc + 1];
            unsigned u0 = umin2(f2ord(fmaf(2.f, acc[mf][nf][0], cs0)),
                                f2ord(fmaf(2.f, acc[mf][nf][1], cs1)));
            unsigned u1 = umin2(f2ord(fmaf(2.f, acc[mf][nf][2], cs0)),
                                f2ord(fmaf(2.f, acc[mf][nf][3], cs1)));
            #pragma unroll
            for (int o = 1; o <= 2; o <<= 1) {
                u0 = umin2(u0, __shfl_xor_sync(0xffffffffu, u0, o));
                u1 = umin2(u1, __shfl_xor_sync(0xffffffffu, u1, o));
            }
            pu0[nf] = u0; pu1[nf] = u1;
        }
        if ((lane & 3) == 0) {
            // truncate (round down) each 8-wide min to its top 16 ord bits
            unsigned long long v0 = (unsigned long long)(pu0[0] >> 16)
                                  | ((unsigned long long)(pu0[1] >> 16) << 16)
                                  | ((unsigned long long)(pu0[2] >> 16) << 32)
                                  | ((unsigned long long)(pu0[3] >> 16) << 48);
            unsigned long long v1 = (unsigned long long)(pu1[0] >> 16)
                                  | ((unsigned long long)(pu1[1] >> 16) << 16)
                                  | ((unsigned long long)(pu1[2] >> 16) << 32)
                                  | ((unsigned long long)(pu1[3] >> 16) << 48);
            const int blk = (nbase + n0) >> 5;
            __stcs(&g_blockmin[(size_t)row0 * NBLK32 + blk], v0);
            __stcs(&g_blockmin[(size_t)(row0 + 8) * NBLK32 + blk], v1);
        }
    }
}

// ---------------------------------------------------------------------------
// Exact fp32 rescue + output gather — one warp per row, two-pass:
// pass 1 scans 64MB packed 16-bit mins (8 x 64-bit per lane); pass 2 rescores
// qualifying 8-wide sub-blocks (4 interleaved codeword chains).
// ---------------------------------------------------------------------------
__global__ void __launch_bounds__(256) rescue_kernel(const float* __restrict__ X,
                                                     const float* __restrict__ CB,
                                                     float* __restrict__ out, int out_size) {
    const int row = blockIdx.x * 8 + (threadIdx.x >> 5);
    const int lane = threadIdx.x & 31;

    float x[16];
    {
        const float4* xr = (const float4*)(X + (size_t)row * C_DIM + lane * 16);
        float4 a = xr[0], b = xr[1], c = xr[2], d = xr[3];
        x[0]=a.x; x[1]=a.y; x[2]=a.z; x[3]=a.w; x[4]=b.x; x[5]=b.y; x[6]=b.z; x[7]=b.w;
        x[8]=c.x; x[9]=c.y; x[10]=c.z; x[11]=c.w; x[12]=d.x; x[13]=d.y; x[14]=d.z; x[15]=d.w;
    }

    const unsigned long long* bm = g_blockmin + (size_t)row * NBLK32;

    // Pass 1: cache 256 packed entries (8 per lane) + 16-bit row min
    unsigned long long vloc[8];
    unsigned m16 = 0xFFFFu;
    #pragma unroll
    for (int r = 0; r < 8; r++) {
        unsigned long long v = __ldcs(&bm[r * 32 + lane]);
        vloc[r] = v;
        unsigned a = umin2((unsigned)(v & 0xFFFFu), (unsigned)((v >> 16) & 0xFFFFu));
        unsigned b = umin2((unsigned)((v >> 32) & 0xFFFFu), (unsigned)(v >> 48));
        m16 = umin2(m16, umin2(a, b));
    }
    #pragma unroll
    for (int o = 16; o; o >>= 1)
        m16 = umin2(m16, __shfl_xor_sync(0xffffffffu, m16, o));
    // row-min lower bound -> threshold in 16-bit ord space (over-inclusive, safe)
    const unsigned thr16 = f2ord(ord2f(m16 << 16) + MARGIN) >> 16;

    // Pass 2: exact rescore of qualifying 8-wide sub-blocks
    float bests = 3.4e38f; int bestk = 0x7FFFFFFF;
    #pragma unroll 1
    for (int r = 0; r < 8; r++) {
        const unsigned long long v = vloc[r];
        const bool any = ((unsigned)(v & 0xFFFFu) <= thr16) |
                         ((unsigned)((v >> 16) & 0xFFFFu) <= thr16) |
                         ((unsigned)((v >> 32) & 0xFFFFu) <= thr16) |
                         ((unsigned)(v >> 48) <= thr16);
        unsigned mask = __ballot_sync(0xffffffffu, any);
        while (mask) {
            int b = __ffs(mask) - 1;
            mask &= mask - 1;
            const unsigned long long vb = __shfl_sync(0xffffffffu, v, b);
            const int k32 = (r * 32 + b) * 32;
            #pragma unroll 1
            for (int h = 0; h < 4; h++) {
                const unsigned hv = (unsigned)((vb >> (16 * h)) & 0xFFFFu);
                if (hv > thr16) continue;
                #pragma unroll 1
                for (int g = 0; g < 2; g++) {
                    const int kg = k32 + h * 8 + g * 4;
                    float p[4];
                    #pragma unroll
                    for (int j = 0; j < 4; j++) {
                        const float4* cr = (const float4*)(CB + (size_t)(kg + j) * C_DIM + lane * 16);
                        float4 c0 = cr[0], c1 = cr[1], c2 = cr[2], c3 = cr[3];
                        float q = 0.f;
                        q = fmaf(x[0],  c0.x, q); q = fmaf(x[1],  c0.y, q);
                        q = fmaf(x[2],  c0.z, q); q = fmaf(x[3],  c0.w, q);
                        q = fmaf(x[4],  c1.x, q); q = fmaf(x[5],  c1.y, q);
                        q = fmaf(x[6],  c1.z, q); q = fmaf(x[7],  c1.w, q);
                        q = fmaf(x[8],  c2.x, q); q = fmaf(x[9],  c2.y, q);
                        q = fmaf(x[10], c2.z, q); q = fmaf(x[11], c2.w, q);
                        q = fmaf(x[12], c3.x, q); q = fmaf(x[13], c3.y, q);
                        q = fmaf(x[14], c3.z, q); q = fmaf(x[15], c3.w, q);
                        p[j] = q;
                    }
                    #pragma unroll
                    for (int o = 16; o; o >>= 1) {
                        p[0] += __shfl_xor_sync(0xffffffffu, p[0], o);
                        p[1] += __shfl_xor_sync(0xffffffffu, p[1], o);
                        p[2] += __shfl_xor_sync(0xffffffffu, p[2], o);
                        p[3] += __shfl_xor_sync(0xffffffffu, p[3], o);
                    }
                    #pragma unroll
                    for (int j = 0; j < 4; j++) {
                        float s = fmaf(2.f, p[j], __ldg(&g_cbsq[kg + j]));
                        int k = kg + j;
                        if (s < bests || (s == bests && k < bestk)) { bests = s; bestk = k; }
                    }
                }
            }
        }
    }

    // ---- output: all lanes hold identical bestk (fully-reduced scores) ----
    const size_t BNC = (size_t)M_TOTAL * C_DIM;
    const float4* cbrow = (const float4*)(CB + (size_t)bestk * C_DIM);
    float4* o0 = (float4*)(out + (size_t)row * C_DIM);
    float4* o1 = (float4*)(out + BNC + (size_t)row * C_DIM);
    const bool dup = ((size_t)out_size >= 2 * BNC);
    #pragma unroll
    for (int i = 0; i < 4; i++) {
        float4 v = cbrow[lane + 32 * i];
        o0[lane + 32 * i] = v;
        if (dup) o1[lane + 32 * i] = v;
    }
    if (lane == 0 && (size_t)out_size >= 2 * BNC + M_TOTAL)
        out[2 * BNC + row] = (float)bestk;
}

// ---------------------------------------------------------------------------
extern "C" void kernel_launch(void* const* d_in, const int* in_sizes, int n_in,
                              void* d_out, int out_size) {
    const float* X  = (const float*)d_in[0];
    const float* CB = (const float*)d_in[1];
    if (n_in >= 2 && in_sizes[0] == K_CB * C_DIM && in_sizes[1] == M_TOTAL * C_DIM) {
        X  = (const float*)d_in[1];
        CB = (const float*)d_in[0];
    }
    float* out = (float*)d_out;

    cudaFuncSetAttribute(gemm_kernel, cudaFuncAttributeMaxDynamicSharedMemorySize, SMEM_TOTAL);

    const long nconv = ((long)M_TOTAL * C_DIM + (long)K_CB * C_DIM) / 4;
    convert_kernel<<<(unsigned)((nconv + 255) / 256), 256>>>(X, CB);
    cbsq_kernel<<<K_CB / 8, 256>>>(CB);
    gemm_kernel<<<dim3(K_CB / BN, M_TOTAL / BM), 256, SMEM_TOTAL>>>();
    rescue_kernel<<<M_TOTAL / 8, 256>>>(X, CB, out, out_size);
}